// round 5
// baseline (speedup 1.0000x reference)
#include <cuda_runtime.h>
#include <cuda_fp16.h>
#include <cstdint>

// ============================================================================
// Reduction: softmax over length-1 key axis == 1  =>  attended = V-projection.
//   a1 = LN( v2 @ (Wo1@Wv2)^T + (Wo1@bv2 + bo1) + v1 ; g1, be1 )
//   a2 = LN( v1 @ (Wo2@Wv1)^T + (Wo2@bv1 + bo2) + v2 ; g2, be2 )
//
// Column-permutation trick (see R4): P makes every lane's MMA A-fragments,
// residual values and outputs contiguous float4s in global memory.
// R5: inputs held as fp16 h2 fragments ONLY (32 regs, not 64) -> 3 CTAs/SM.
// Residual taken from the fp16 value (adds ~1e-4 rms, budget 1e-3).
// ============================================================================

#define EMBED 64
#define TILE_M 128
#define STRIDE 72  // halves per smem row of M (144B: conflict-free ldmatrix)

__device__ __host__ __forceinline__ int permP(int l) {
    return (l & 48) | ((l & 6) << 1) | ((l & 8) >> 2) | (l & 1);
}

// ---------------- device scratch for folded weights -------------------------
__device__ __half g_Mp[2][EMBED * EMBED];  // [n_l][k_l], both dims P-permuted
__device__ float  g_bias[2][EMBED];        // physical order

// ---------------- prep: fold Wo@Wv -> permuted fp16, Wo@bv + bo -> f32 ------
__global__ void prep_kernel(const float* __restrict__ Wo1, const float* __restrict__ Wv2,
                            const float* __restrict__ bv2, const float* __restrict__ bo1,
                            const float* __restrict__ Wo2, const float* __restrict__ Wv1,
                            const float* __restrict__ bv1, const float* __restrict__ bo2) {
    if (blockIdx.x == 16) {
        int t = threadIdx.x;
        if (t < EMBED) {
            float a1[4] = {bo1[t], 0.f, 0.f, 0.f};
            float a2[4] = {bo2[t], 0.f, 0.f, 0.f};
#pragma unroll
            for (int i = 0; i < EMBED; i += 4) {
#pragma unroll
                for (int u = 0; u < 4; u++) {
                    a1[u] = fmaf(Wo1[t * 64 + i + u], bv2[i + u], a1[u]);
                    a2[u] = fmaf(Wo2[t * 64 + i + u], bv1[i + u], a2[u]);
                }
            }
            g_bias[0][t] = (a1[0] + a1[1]) + (a1[2] + a1[3]);
            g_bias[1][t] = (a2[0] + a2[1]) + (a2[2] + a2[3]);
        }
        return;
    }
    int idx = blockIdx.x * 256 + threadIdx.x;  // 4096 elements
    int jp = permP(idx >> 6), kp = permP(idx & 63);
    float s1[4] = {0.f, 0.f, 0.f, 0.f}, s2[4] = {0.f, 0.f, 0.f, 0.f};
#pragma unroll
    for (int i = 0; i < EMBED; i += 4) {
#pragma unroll
        for (int u = 0; u < 4; u++) {
            s1[u] = fmaf(Wo1[jp * 64 + i + u], Wv2[(i + u) * 64 + kp], s1[u]);
            s2[u] = fmaf(Wo2[jp * 64 + i + u], Wv1[(i + u) * 64 + kp], s2[u]);
        }
    }
    g_Mp[0][idx] = __float2half_rn((s1[0] + s1[1]) + (s1[2] + s1[3]));
    g_Mp[1][idx] = __float2half_rn((s2[0] + s2[1]) + (s2[2] + s2[3]));
}

// ---------------- asm helpers ------------------------------------------------
__device__ __forceinline__ void mma16816(float* d, const uint32_t* a, const uint32_t* b) {
    asm volatile(
        "mma.sync.aligned.m16n8k16.row.col.f32.f16.f16.f32 "
        "{%0,%1,%2,%3}, {%4,%5,%6,%7}, {%8,%9}, {%0,%1,%2,%3};"
        : "+f"(d[0]), "+f"(d[1]), "+f"(d[2]), "+f"(d[3])
        : "r"(a[0]), "r"(a[1]), "r"(a[2]), "r"(a[3]), "r"(b[0]), "r"(b[1]));
}
__device__ __forceinline__ float4 ldcs_f4(const float* p) {
    float4 r;
    asm volatile("ld.global.cs.v4.f32 {%0,%1,%2,%3}, [%4];"
                 : "=f"(r.x), "=f"(r.y), "=f"(r.z), "=f"(r.w) : "l"(p));
    return r;
}
__device__ __forceinline__ void stcs_f4(float* p, float4 v) {
    asm volatile("st.global.cs.v4.f32 [%0], {%1,%2,%3,%4};"
                 :: "l"(p), "f"(v.x), "f"(v.y), "f"(v.z), "f"(v.w) : "memory");
}
__device__ __forceinline__ uint32_t smem_u32(const void* p) {
    uint32_t a;
    asm("{ .reg .u64 t; cvta.to.shared.u64 t, %1; cvt.u32.u64 %0, t; }"
        : "=r"(a) : "l"(p));
    return a;
}
__device__ __forceinline__ void ldmatrix_x4(uint32_t* b, uint32_t addr) {
    asm volatile("ldmatrix.sync.aligned.m8n8.x4.shared.b16 {%0,%1,%2,%3}, [%4];"
                 : "=r"(b[0]), "=r"(b[1]), "=r"(b[2]), "=r"(b[3]) : "r"(addr));
}
__device__ __forceinline__ uint32_t packh2(float a, float b) {
    __half2 h = __floats2half2_rn(a, b);
    return *reinterpret_cast<uint32_t*>(&h);
}
__device__ __forceinline__ float2 unph2(uint32_t u) {
    return __half22float2(*reinterpret_cast<__half2*>(&u));
}

struct SmemLayout {
    __half M[2][EMBED * STRIDE];  // P-permuted folded weights
    float  cb[2][EMBED];          // physical order
    float  gm[2][EMBED];
    float  bt[2][EMBED];
};

__global__ void __launch_bounds__(256, 3)
fused_kernel(const float* __restrict__ v1, const float* __restrict__ v2,
             const float* __restrict__ g1, const float* __restrict__ be1,
             const float* __restrict__ g2, const float* __restrict__ be2,
             float* __restrict__ out, int Btot) {
    __shared__ SmemLayout sm;
    const int tid = threadIdx.x;
    const int wid = tid >> 5, lane = tid & 31;
    const int g = lane >> 2, tq = lane & 3;
    const int wrow = wid * 16;
    const size_t row0 = (size_t)blockIdx.x * TILE_M;

    // --- inputs: 8 LDG.128 per tensor per thread, immediately packed to h2
    //     in A-fragment layout. [kt][s]: s0 = row g k-lo, s1 = row g+8 k-lo,
    //     s2 = row g k-hi, s3 = row g+8 k-hi.
    uint32_t v1h[4][4], v2h[4][4];
    {
        const float* b1 = v1 + (row0 + wrow + g) * EMBED + tq * 4;
        const float* b2 = v2 + (row0 + wrow + g) * EMBED + tq * 4;
#pragma unroll
        for (int kt = 0; kt < 4; kt++) {
            float4 f0 = ldcs_f4(b1 + kt * 16);
            float4 f1 = ldcs_f4(b1 + 8 * EMBED + kt * 16);
            v1h[kt][0] = packh2(f0.x, f0.y);
            v1h[kt][1] = packh2(f1.x, f1.y);
            v1h[kt][2] = packh2(f0.z, f0.w);
            v1h[kt][3] = packh2(f1.z, f1.w);
            float4 h0 = ldcs_f4(b2 + kt * 16);
            float4 h1 = ldcs_f4(b2 + 8 * EMBED + kt * 16);
            v2h[kt][0] = packh2(h0.x, h0.y);
            v2h[kt][1] = packh2(h1.x, h1.y);
            v2h[kt][2] = packh2(h0.z, h0.w);
            v2h[kt][3] = packh2(h1.z, h1.w);
        }
    }

    // --- permuted weights into padded smem ---
#pragma unroll
    for (int m = 0; m < 2; m++) {
        uint32_t* dst = (uint32_t*)sm.M[m];
        const uint32_t* srcw = (const uint32_t*)g_Mp[m];
        for (int i = tid; i < 2048; i += 256) {
            int j = i >> 5, k2 = i & 31;
            dst[j * (STRIDE / 2) + k2] = srcw[i];
        }
    }
    if (tid < 64) {
        sm.cb[0][tid] = g_bias[0][tid];
        sm.cb[1][tid] = g_bias[1][tid];
        sm.gm[0][tid] = g1[tid];
        sm.gm[1][tid] = g2[tid];
        sm.bt[0][tid] = be1[tid];
        sm.bt[1][tid] = be2[tid];
    }
    __syncthreads();

    const uint32_t smM0 = smem_u32(sm.M[0]);
    const uint32_t lmoff = (uint32_t)((lane & 7) * (STRIDE * 2) +
                                      ((lane >> 4) & 1) * 32 +
                                      ((lane >> 3) & 1) * 16);

#pragma unroll
    for (int o = 0; o < 2; o++) {
        // o=0: A = v2 (GEMM), residual = v1 ; o=1: swapped.
        const uint32_t (*Ah)[4] = o ? v1h : v2h;
        const uint32_t (*Rh)[4] = o ? v2h : v1h;
        const uint32_t smM = smM0 + (uint32_t)o * (EMBED * STRIDE * 2);

        float acc[8][4];
#pragma unroll
        for (int nt = 0; nt < 8; nt++)
#pragma unroll
            for (int q = 0; q < 4; q++) acc[nt][q] = 0.f;

#pragma unroll
        for (int ktp = 0; ktp < 2; ktp++) {
#pragma unroll
            for (int nt = 0; nt < 8; nt++) {
                uint32_t b[4];
                ldmatrix_x4(b, smM + lmoff + (uint32_t)(nt * 8 * STRIDE * 2 + ktp * 64));
                mma16816(acc[nt], Ah[2 * ktp], b);
                mma16816(acc[nt], Ah[2 * ktp + 1], b + 2);
            }
        }

        // --- epilogue: bias + residual (from fp16) folded into acc, then LN ---
        const float4* cb4 = (const float4*)sm.cb[o];
        float s0 = 0.f, ss0 = 0.f, s1 = 0.f, ss1 = 0.f;
#pragma unroll
        for (int kt = 0; kt < 4; kt++) {
            float4 c = cb4[kt * 4 + tq];
            float2 rA = unph2(Rh[kt][0]);  // row g,   cols +0,+1
            float2 rB = unph2(Rh[kt][2]);  // row g,   cols +2,+3
            float2 rC = unph2(Rh[kt][1]);  // row g+8, cols +0,+1
            float2 rD = unph2(Rh[kt][3]);  // row g+8, cols +2,+3
            acc[2 * kt][0] += c.x + rA.x;
            acc[2 * kt][1] += c.y + rA.y;
            acc[2 * kt + 1][0] += c.z + rB.x;
            acc[2 * kt + 1][1] += c.w + rB.y;
            acc[2 * kt][2] += c.x + rC.x;
            acc[2 * kt][3] += c.y + rC.y;
            acc[2 * kt + 1][2] += c.z + rD.x;
            acc[2 * kt + 1][3] += c.w + rD.y;
            s0 += acc[2 * kt][0] + acc[2 * kt][1] + acc[2 * kt + 1][0] + acc[2 * kt + 1][1];
            ss0 += acc[2 * kt][0] * acc[2 * kt][0] + acc[2 * kt][1] * acc[2 * kt][1] +
                   acc[2 * kt + 1][0] * acc[2 * kt + 1][0] + acc[2 * kt + 1][1] * acc[2 * kt + 1][1];
            s1 += acc[2 * kt][2] + acc[2 * kt][3] + acc[2 * kt + 1][2] + acc[2 * kt + 1][3];
            ss1 += acc[2 * kt][2] * acc[2 * kt][2] + acc[2 * kt][3] * acc[2 * kt][3] +
                   acc[2 * kt + 1][2] * acc[2 * kt + 1][2] + acc[2 * kt + 1][3] * acc[2 * kt + 1][3];
        }
        s0  += __shfl_xor_sync(0xFFFFFFFFu, s0, 1);
        s0  += __shfl_xor_sync(0xFFFFFFFFu, s0, 2);
        ss0 += __shfl_xor_sync(0xFFFFFFFFu, ss0, 1);
        ss0 += __shfl_xor_sync(0xFFFFFFFFu, ss0, 2);
        s1  += __shfl_xor_sync(0xFFFFFFFFu, s1, 1);
        s1  += __shfl_xor_sync(0xFFFFFFFFu, s1, 2);
        ss1 += __shfl_xor_sync(0xFFFFFFFFu, ss1, 1);
        ss1 += __shfl_xor_sync(0xFFFFFFFFu, ss1, 2);
        float mu0 = s0 * (1.f / 64.f);
        float mu1 = s1 * (1.f / 64.f);
        float rs0 = rsqrtf(ss0 * (1.f / 64.f) - mu0 * mu0 + 1e-5f);
        float rs1 = rsqrtf(ss1 * (1.f / 64.f) - mu1 * mu1 + 1e-5f);

        const float4* gm4 = (const float4*)sm.gm[o];
        const float4* bt4 = (const float4*)sm.bt[o];
        float* outp = out + (o ? (size_t)Btot * EMBED : 0) +
                      (row0 + wrow + g) * EMBED + tq * 4;
#pragma unroll
        for (int kt = 0; kt < 4; kt++) {
            float4 G = gm4[kt * 4 + tq], T = bt4[kt * 4 + tq];
            float4 y0, y1;
            y0.x = (acc[2 * kt][0] - mu0) * rs0 * G.x + T.x;
            y0.y = (acc[2 * kt][1] - mu0) * rs0 * G.y + T.y;
            y0.z = (acc[2 * kt + 1][0] - mu0) * rs0 * G.z + T.z;
            y0.w = (acc[2 * kt + 1][1] - mu0) * rs0 * G.w + T.w;
            y1.x = (acc[2 * kt][2] - mu1) * rs1 * G.x + T.x;
            y1.y = (acc[2 * kt][3] - mu1) * rs1 * G.y + T.y;
            y1.z = (acc[2 * kt + 1][2] - mu1) * rs1 * G.z + T.z;
            y1.w = (acc[2 * kt + 1][3] - mu1) * rs1 * G.w + T.w;
            stcs_f4(outp + kt * 16, y0);
            stcs_f4(outp + 8 * EMBED + kt * 16, y1);
        }
    }
}

// ---------------- launcher ---------------------------------------------------
extern "C" void kernel_launch(void* const* d_in, const int* in_sizes, int n_in,
                              void* d_out, int out_size) {
    // 0 v1, 1 v2, 2 Wq1, 3 bq1, 4 Wk2, 5 bk2, 6 Wv2, 7 bv2, 8 Wo1, 9 bo1,
    // 10 Wq2, 11 bq2, 12 Wk1, 13 bk1, 14 Wv1, 15 bv1, 16 Wo2, 17 bo2,
    // 18 g1, 19 be1, 20 g2, 21 be2
    const float* v1  = (const float*)d_in[0];
    const float* v2  = (const float*)d_in[1];
    const float* Wv2 = (const float*)d_in[6];
    const float* bv2 = (const float*)d_in[7];
    const float* Wo1 = (const float*)d_in[8];
    const float* bo1 = (const float*)d_in[9];
    const float* Wv1 = (const float*)d_in[14];
    const float* bv1 = (const float*)d_in[15];
    const float* Wo2 = (const float*)d_in[16];
    const float* bo2 = (const float*)d_in[17];
    const float* g1  = (const float*)d_in[18];
    const float* be1 = (const float*)d_in[19];
    const float* g2  = (const float*)d_in[20];
    const float* be2 = (const float*)d_in[21];
    float* out = (float*)d_out;

    int Btot = in_sizes[0] / EMBED;

    prep_kernel<<<17, 256>>>(Wo1, Wv2, bv2, bo1, Wo2, Wv1, bv1, bo2);
    fused_kernel<<<Btot / TILE_M, 256>>>(v1, v2, g1, be1, g2, be2, out, Btot);
}

// round 6
// speedup vs baseline: 1.3278x; 1.3278x over previous
#include <cuda_runtime.h>
#include <cuda_fp16.h>
#include <cstdint>

// ============================================================================
// Reduction: softmax over length-1 key axis == 1  =>  attended = V-projection.
//   a1 = LN( v2 @ (Wo1@Wv2)^T + (Wo1@bv2 + bo1) + v1 ; g1, be1 )
//   a2 = LN( v1 @ (Wo2@Wv1)^T + (Wo2@bv1 + bo2) + v2 ; g2, be2 )
//
// Column-permutation trick (R4): P = {b1 b0|h|t1 t0|j} -> {b1 b0|t1 t0|h|j}
// makes every lane's MMA A-fragments / residual / outputs contiguous float4s.
// R6: PERSISTENT CTAs (304 = 2/SM), weights->smem once, NO per-tile barrier;
// per-warp software pipeline: tile t+D loads in flight during tile t compute.
// ============================================================================

#define EMBED 64
#define TILE_M 128
#define STRIDE 72   // halves per smem row of M (144B: conflict-free ldmatrix)
#define NCTA 304    // 2 per SM on GB300 (152 SMs)

__device__ __host__ __forceinline__ int permP(int l) {
    return (l & 48) | ((l & 6) << 1) | ((l & 8) >> 2) | (l & 1);
}

// ---------------- device scratch for folded weights -------------------------
__device__ __half g_Mp[2][EMBED * EMBED];  // [n_l][k_l], both dims P-permuted
__device__ float  g_bias[2][EMBED];        // physical order

// ---------------- prep: fold Wo@Wv -> permuted fp16, Wo@bv + bo -> f32 ------
__global__ void prep_kernel(const float* __restrict__ Wo1, const float* __restrict__ Wv2,
                            const float* __restrict__ bv2, const float* __restrict__ bo1,
                            const float* __restrict__ Wo2, const float* __restrict__ Wv1,
                            const float* __restrict__ bv1, const float* __restrict__ bo2) {
    if (blockIdx.x == 16) {
        int t = threadIdx.x;
        if (t < EMBED) {
            float a1[4] = {bo1[t], 0.f, 0.f, 0.f};
            float a2[4] = {bo2[t], 0.f, 0.f, 0.f};
#pragma unroll
            for (int i = 0; i < EMBED; i += 4) {
#pragma unroll
                for (int u = 0; u < 4; u++) {
                    a1[u] = fmaf(Wo1[t * 64 + i + u], bv2[i + u], a1[u]);
                    a2[u] = fmaf(Wo2[t * 64 + i + u], bv1[i + u], a2[u]);
                }
            }
            g_bias[0][t] = (a1[0] + a1[1]) + (a1[2] + a1[3]);
            g_bias[1][t] = (a2[0] + a2[1]) + (a2[2] + a2[3]);
        }
        return;
    }
    int idx = blockIdx.x * 256 + threadIdx.x;  // 4096 elements
    int jp = permP(idx >> 6), kp = permP(idx & 63);
    float s1[4] = {0.f, 0.f, 0.f, 0.f}, s2[4] = {0.f, 0.f, 0.f, 0.f};
#pragma unroll
    for (int i = 0; i < EMBED; i += 4) {
#pragma unroll
        for (int u = 0; u < 4; u++) {
            s1[u] = fmaf(Wo1[jp * 64 + i + u], Wv2[(i + u) * 64 + kp], s1[u]);
            s2[u] = fmaf(Wo2[jp * 64 + i + u], Wv1[(i + u) * 64 + kp], s2[u]);
        }
    }
    g_Mp[0][idx] = __float2half_rn((s1[0] + s1[1]) + (s1[2] + s1[3]));
    g_Mp[1][idx] = __float2half_rn((s2[0] + s2[1]) + (s2[2] + s2[3]));
}

// ---------------- asm helpers ------------------------------------------------
__device__ __forceinline__ void mma16816(float* d, const uint32_t* a, const uint32_t* b) {
    asm volatile(
        "mma.sync.aligned.m16n8k16.row.col.f32.f16.f16.f32 "
        "{%0,%1,%2,%3}, {%4,%5,%6,%7}, {%8,%9}, {%0,%1,%2,%3};"
        : "+f"(d[0]), "+f"(d[1]), "+f"(d[2]), "+f"(d[3])
        : "r"(a[0]), "r"(a[1]), "r"(a[2]), "r"(a[3]), "r"(b[0]), "r"(b[1]));
}
__device__ __forceinline__ float4 ldcs_f4(const float* p) {
    float4 r;
    asm volatile("ld.global.cs.v4.f32 {%0,%1,%2,%3}, [%4];"
                 : "=f"(r.x), "=f"(r.y), "=f"(r.z), "=f"(r.w) : "l"(p));
    return r;
}
__device__ __forceinline__ void stcs_f4(float* p, float4 v) {
    asm volatile("st.global.cs.v4.f32 [%0], {%1,%2,%3,%4};"
                 :: "l"(p), "f"(v.x), "f"(v.y), "f"(v.z), "f"(v.w) : "memory");
}
__device__ __forceinline__ uint32_t smem_u32(const void* p) {
    uint32_t a;
    asm("{ .reg .u64 t; cvta.to.shared.u64 t, %1; cvt.u32.u64 %0, t; }"
        : "=r"(a) : "l"(p));
    return a;
}
__device__ __forceinline__ void ldmatrix_x4(uint32_t* b, uint32_t addr) {
    asm volatile("ldmatrix.sync.aligned.m8n8.x4.shared.b16 {%0,%1,%2,%3}, [%4];"
                 : "=r"(b[0]), "=r"(b[1]), "=r"(b[2]), "=r"(b[3]) : "r"(addr));
}
__device__ __forceinline__ uint32_t packh2(float a, float b) {
    __half2 h = __floats2half2_rn(a, b);
    return *reinterpret_cast<uint32_t*>(&h);
}
__device__ __forceinline__ float2 unph2(uint32_t u) {
    return __half22float2(*reinterpret_cast<__half2*>(&u));
}

struct SmemLayout {
    __half M[2][EMBED * STRIDE];  // P-permuted folded weights
    float  cb[2][EMBED];          // physical order
    float  gm[2][EMBED];
    float  bt[2][EMBED];
};

// issue 8 LDG.128 for one tensor's warp-rows of a tile (no wait)
__device__ __forceinline__ void issue_tile(const float* base, float4* q) {
#pragma unroll
    for (int kt = 0; kt < 4; kt++) {
        q[2 * kt]     = ldcs_f4(base + kt * 16);
        q[2 * kt + 1] = ldcs_f4(base + 8 * EMBED + kt * 16);
    }
}
__device__ __forceinline__ void pack_tile(const float4* q, uint32_t h[4][4]) {
#pragma unroll
    for (int kt = 0; kt < 4; kt++) {
        float4 f0 = q[2 * kt], f1 = q[2 * kt + 1];
        h[kt][0] = packh2(f0.x, f0.y);
        h[kt][1] = packh2(f1.x, f1.y);
        h[kt][2] = packh2(f0.z, f0.w);
        h[kt][3] = packh2(f1.z, f1.w);
    }
}

// one output: GEMM(A) + bias + residual(R) + LayerNorm + store
__device__ __forceinline__ void compute_store(
    const uint32_t Ah[4][4], const uint32_t Rh[4][4],
    uint32_t smM, uint32_t lmoff,
    const float4* cb4, const float4* gm4, const float4* bt4,
    int tq, float* __restrict__ outp) {
    float acc[8][4];
#pragma unroll
    for (int nt = 0; nt < 8; nt++)
#pragma unroll
        for (int q = 0; q < 4; q++) acc[nt][q] = 0.f;

#pragma unroll
    for (int ktp = 0; ktp < 2; ktp++) {
#pragma unroll
        for (int nt = 0; nt < 8; nt++) {
            uint32_t b[4];
            ldmatrix_x4(b, smM + lmoff + (uint32_t)(nt * 8 * STRIDE * 2 + ktp * 64));
            mma16816(acc[nt], Ah[2 * ktp], b);
            mma16816(acc[nt], Ah[2 * ktp + 1], b + 2);
        }
    }

    float s0 = 0.f, ss0 = 0.f, s1 = 0.f, ss1 = 0.f;
#pragma unroll
    for (int kt = 0; kt < 4; kt++) {
        float4 c = cb4[kt * 4 + tq];
        float2 rA = unph2(Rh[kt][0]);
        float2 rB = unph2(Rh[kt][2]);
        float2 rC = unph2(Rh[kt][1]);
        float2 rD = unph2(Rh[kt][3]);
        acc[2 * kt][0] += c.x + rA.x;
        acc[2 * kt][1] += c.y + rA.y;
        acc[2 * kt + 1][0] += c.z + rB.x;
        acc[2 * kt + 1][1] += c.w + rB.y;
        acc[2 * kt][2] += c.x + rC.x;
        acc[2 * kt][3] += c.y + rC.y;
        acc[2 * kt + 1][2] += c.z + rD.x;
        acc[2 * kt + 1][3] += c.w + rD.y;
        s0 += acc[2 * kt][0] + acc[2 * kt][1] + acc[2 * kt + 1][0] + acc[2 * kt + 1][1];
        ss0 += acc[2 * kt][0] * acc[2 * kt][0] + acc[2 * kt][1] * acc[2 * kt][1] +
               acc[2 * kt + 1][0] * acc[2 * kt + 1][0] + acc[2 * kt + 1][1] * acc[2 * kt + 1][1];
        s1 += acc[2 * kt][2] + acc[2 * kt][3] + acc[2 * kt + 1][2] + acc[2 * kt + 1][3];
        ss1 += acc[2 * kt][2] * acc[2 * kt][2] + acc[2 * kt][3] * acc[2 * kt][3] +
               acc[2 * kt + 1][2] * acc[2 * kt + 1][2] + acc[2 * kt + 1][3] * acc[2 * kt + 1][3];
    }
    s0  += __shfl_xor_sync(0xFFFFFFFFu, s0, 1);
    s0  += __shfl_xor_sync(0xFFFFFFFFu, s0, 2);
    ss0 += __shfl_xor_sync(0xFFFFFFFFu, ss0, 1);
    ss0 += __shfl_xor_sync(0xFFFFFFFFu, ss0, 2);
    s1  += __shfl_xor_sync(0xFFFFFFFFu, s1, 1);
    s1  += __shfl_xor_sync(0xFFFFFFFFu, s1, 2);
    ss1 += __shfl_xor_sync(0xFFFFFFFFu, ss1, 1);
    ss1 += __shfl_xor_sync(0xFFFFFFFFu, ss1, 2);
    float mu0 = s0 * (1.f / 64.f);
    float mu1 = s1 * (1.f / 64.f);
    float rs0 = rsqrtf(ss0 * (1.f / 64.f) - mu0 * mu0 + 1e-5f);
    float rs1 = rsqrtf(ss1 * (1.f / 64.f) - mu1 * mu1 + 1e-5f);

#pragma unroll
    for (int kt = 0; kt < 4; kt++) {
        float4 G = gm4[kt * 4 + tq], T = bt4[kt * 4 + tq];
        float4 y0, y1;
        y0.x = (acc[2 * kt][0] - mu0) * rs0 * G.x + T.x;
        y0.y = (acc[2 * kt][1] - mu0) * rs0 * G.y + T.y;
        y0.z = (acc[2 * kt + 1][0] - mu0) * rs0 * G.z + T.z;
        y0.w = (acc[2 * kt + 1][1] - mu0) * rs0 * G.w + T.w;
        y1.x = (acc[2 * kt][2] - mu1) * rs1 * G.x + T.x;
        y1.y = (acc[2 * kt][3] - mu1) * rs1 * G.y + T.y;
        y1.z = (acc[2 * kt + 1][2] - mu1) * rs1 * G.z + T.z;
        y1.w = (acc[2 * kt + 1][3] - mu1) * rs1 * G.w + T.w;
        stcs_f4(outp + kt * 16, y0);
        stcs_f4(outp + 8 * EMBED + kt * 16, y1);
    }
}

__global__ void __launch_bounds__(256, 2)
fused_kernel(const float* __restrict__ v1, const float* __restrict__ v2,
             const float* __restrict__ g1, const float* __restrict__ be1,
             const float* __restrict__ g2, const float* __restrict__ be2,
             float* __restrict__ out, int Btot) {
    __shared__ SmemLayout sm;
    const int tid = threadIdx.x;
    const int wid = tid >> 5, lane = tid & 31;
    const int g = lane >> 2, tq = lane & 3;
    const int wrow = wid * 16;
    const int ntiles = Btot / TILE_M;

    // --- weights + constants into smem ONCE per persistent CTA ---
#pragma unroll
    for (int m = 0; m < 2; m++) {
        uint32_t* dst = (uint32_t*)sm.M[m];
        const uint32_t* srcw = (const uint32_t*)g_Mp[m];
        for (int i = tid; i < 2048; i += 256) {
            int j = i >> 5, k2 = i & 31;
            dst[j * (STRIDE / 2) + k2] = srcw[i];
        }
    }
    if (tid < 64) {
        sm.cb[0][tid] = g_bias[0][tid];
        sm.cb[1][tid] = g_bias[1][tid];
        sm.gm[0][tid] = g1[tid];
        sm.gm[1][tid] = g2[tid];
        sm.bt[0][tid] = be1[tid];
        sm.bt[1][tid] = be2[tid];
    }
    __syncthreads();  // the ONLY block barrier

    const uint32_t smM0 = smem_u32(sm.M[0]);
    const uint32_t smM1 = smM0 + (uint32_t)(EMBED * STRIDE * 2);
    const uint32_t lmoff = (uint32_t)((lane & 7) * (STRIDE * 2) +
                                      ((lane >> 4) & 1) * 32 +
                                      ((lane >> 3) & 1) * 16);
    const float4* cb0 = (const float4*)sm.cb[0];
    const float4* cb1 = (const float4*)sm.cb[1];
    const float4* gm0 = (const float4*)sm.gm[0];
    const float4* gm1 = (const float4*)sm.gm[1];
    const float4* bt0 = (const float4*)sm.bt[0];
    const float4* bt1 = (const float4*)sm.bt[1];

    const int lrow = wrow + g;                 // warp-lane row within tile
    const size_t lcol = (size_t)tq * 4;
    const size_t o2off = (size_t)Btot * EMBED;

    int tile = blockIdx.x;
    if (tile >= ntiles) return;

    // --- prologue: load tile's both tensors, pack to fp16 fragments ---
    uint32_t cur1[4][4], cur2[4][4];
    {
        float4 q[16];
        const size_t base = ((size_t)tile * TILE_M + lrow) * EMBED + lcol;
        issue_tile(v1 + base, q);
        issue_tile(v2 + base, q + 8);
        pack_tile(q, cur1);
        pack_tile(q + 8, cur2);
    }

    for (;;) {
        const int next = tile + NCTA;
        const bool has_next = next < ntiles;
        const size_t nbase = ((size_t)(has_next ? next : tile) * TILE_M + lrow) * EMBED + lcol;
        const size_t obase = ((size_t)tile * TILE_M + lrow) * EMBED + lcol;

        // prefetch v2(next) while computing output 1 of current tile
        float4 qa[8];
        issue_tile(v2 + nbase, qa);
        compute_store(cur2, cur1, smM0, lmoff, cb0, gm0, bt0, tq, out + obase);
        uint32_t nv2[4][4];
        pack_tile(qa, nv2);

        // prefetch v1(next) while computing output 2 of current tile
        float4 qb[8];
        issue_tile(v1 + nbase, qb);
        compute_store(cur1, cur2, smM1, lmoff, cb1, gm1, bt1, tq, out + o2off + obase);

        if (!has_next) break;
        pack_tile(qb, cur1);
#pragma unroll
        for (int kt = 0; kt < 4; kt++)
#pragma unroll
            for (int s = 0; s < 4; s++) cur2[kt][s] = nv2[kt][s];
        tile = next;
    }
}

// ---------------- launcher ---------------------------------------------------
extern "C" void kernel_launch(void* const* d_in, const int* in_sizes, int n_in,
                              void* d_out, int out_size) {
    // 0 v1, 1 v2, 2 Wq1, 3 bq1, 4 Wk2, 5 bk2, 6 Wv2, 7 bv2, 8 Wo1, 9 bo1,
    // 10 Wq2, 11 bq2, 12 Wk1, 13 bk1, 14 Wv1, 15 bv1, 16 Wo2, 17 bo2,
    // 18 g1, 19 be1, 20 g2, 21 be2
    const float* v1  = (const float*)d_in[0];
    const float* v2  = (const float*)d_in[1];
    const float* Wv2 = (const float*)d_in[6];
    const float* bv2 = (const float*)d_in[7];
    const float* Wo1 = (const float*)d_in[8];
    const float* bo1 = (const float*)d_in[9];
    const float* Wv1 = (const float*)d_in[14];
    const float* bv1 = (const float*)d_in[15];
    const float* Wo2 = (const float*)d_in[16];
    const float* bo2 = (const float*)d_in[17];
    const float* g1  = (const float*)d_in[18];
    const float* be1 = (const float*)d_in[19];
    const float* g2  = (const float*)d_in[20];
    const float* be2 = (const float*)d_in[21];
    float* out = (float*)d_out;

    int Btot = in_sizes[0] / EMBED;

    prep_kernel<<<17, 256>>>(Wo1, Wv2, bv2, bo1, Wo2, Wv1, bv1, bo2);
    fused_kernel<<<NCTA, 256>>>(v1, v2, g1, be1, g2, be2, out, Btot);
}